// round 13
// baseline (speedup 1.0000x reference)
#include <cuda_runtime.h>
#include <stdint.h>

// ---------------------------------------------------------------------------
// W4A8 per-group GEMM, legacy IMMA, WARP-SPECIALIZED producer/consumer.
//   w_int8[o,k] = q4[o,k]*s2[g,o] + z[g,o]   (exact int8, |w| <= 105)
//   acc[m,o]    = sum_k x_i8[m,k]*w_int8[o,k]  (s32 mma.m16n8k32)
//   out[m,o]    = acc * isc[m] * s1[o] + bias[o]
//
// R8 analysis: tensor busy is a hard 47.8us wall, but elapsed was 65us because
// dequant/STS phases alternate with MMA behind __syncthreads. Round 13:
//  - warps 0-3 = consumers: ONLY ldmatrix+IMMA (m16 x n32 each), never touch
//    gmem until the epilogue
//  - warps 4-7 = producers: cp.async raw qweight -> dequant -> STS B;
//    LDG packed x -> STS A; scales
//  - handoff via named barriers (FULL 1/2, EMPTY 3/4; 128 arrive + 128 sync)
// Tensor pipe should now run near-continuously: target ~50us.
// ---------------------------------------------------------------------------

#define M_DIM 64
#define K_DIM 4096
#define N_DIM 14336
#define G_DIM 32
#define NT    32             // output channels per CTA -> 448 CTAs
#define BROW  144            // padded s8 tile row (conflict-free, validated)
#define THREADS 256
#define TILE_A 9216          // 64 x 144
#define TILE_B 4608          // 32 x 144
#define OFF_RAW(b) ((b) * 16384)
#define OFF_A(b)   (32768 + (b) * TILE_A)
#define OFF_B(b)   (51200 + (b) * TILE_B)
#define SMEM_TOTAL 60416

#define CP_ASYNC16(dst, src) \
    asm volatile("cp.async.cg.shared.global [%0], [%1], 16;" :: "r"(dst), "l"(src))
#define CP_COMMIT()  asm volatile("cp.async.commit_group;")
#define CP_WAIT(N)   asm volatile("cp.async.wait_group %0;" :: "n"(N))
#define BAR_SYNC(id)   asm volatile("bar.sync %0, %1;"   :: "r"(id), "r"(THREADS) : "memory")
#define BAR_ARRIVE(id) asm volatile("bar.arrive %0, %1;" :: "r"(id), "r"(THREADS) : "memory")

__device__ __forceinline__ unsigned smem_u32(const void* p) {
    unsigned a;
    asm("{ .reg .u64 t; cvta.to.shared.u64 t, %1; cvt.u32.u64 %0, t; }" : "=r"(a) : "l"(p));
    return a;
}

// int8-packed activations [M][K] (256 KB static scratch; validated R1-R8)
__device__ __align__(16) unsigned int g_x_packed[M_DIM * K_DIM / 4];

__global__ void pack_x_kernel(const int* __restrict__ x) {
    int idx = blockIdx.x * blockDim.x + threadIdx.x;
    if (idx >= M_DIM * K_DIM / 4) return;
    const int4 v = reinterpret_cast<const int4*>(x)[idx];
    unsigned a = __byte_perm((unsigned)v.x, (unsigned)v.y, 0x0040);
    unsigned b = __byte_perm((unsigned)v.z, (unsigned)v.w, 0x0040);
    g_x_packed[idx] = __byte_perm(a, b, 0x5410);
}

// ---- main GEMM ---------------------------------------------------------------
__global__ __launch_bounds__(THREADS, 3)
void w4a8_gemm_kernel(const int*   __restrict__ qw,    // [N,K] int32 (0..15)
                      const int*   __restrict__ s2s,   // [G,N]
                      const int*   __restrict__ s2z,   // [G,N]
                      const float* __restrict__ isc,   // [M]
                      const float* __restrict__ s1,    // [N]
                      const float* __restrict__ bias,  // [N]
                      float*       __restrict__ out)   // [M,N]
{
    extern __shared__ __align__(16) unsigned char smem[];
    const unsigned sbase = smem_u32(smem);

    const int tid  = threadIdx.x;
    const int warp = tid >> 5;
    const int lane = tid & 31;
    const int n0   = blockIdx.x * NT;

    if (warp < 4) {
        // =================== CONSUMER: warps 0-3, pure MMA ===================
        const int wm = warp;                 // m16 block
        const int g4 = lane >> 2, tg = lane & 3;

        // ldmatrix bases (buffer 0) — layouts validated in R8
        const unsigned aFrag = sbase + OFF_A(0)
            + (unsigned)(wm * 16 + (lane & 15)) * BROW
            + (unsigned)((lane >> 4) & 1) * 16;
        const unsigned bFragLo = sbase + OFF_B(0)
            + (unsigned)(((lane >> 4) & 1) * 8 + (lane & 7)) * BROW
            + (unsigned)((lane >> 3) & 1) * 16;

        int acc[4][4];
#pragma unroll
        for (int i = 0; i < 4; i++)
#pragma unroll
            for (int j = 0; j < 4; j++) acc[i][j] = 0;

        for (int g = 0; g < G_DIM; ++g) {
            const int b = g & 1;
            BAR_SYNC(1 + b);                 // wait FULL[b]

            const unsigned aOff = aFrag + (unsigned)b * TILE_A;
            const unsigned bLo  = bFragLo + (unsigned)b * TILE_B;
#pragma unroll
            for (int ks = 0; ks < 4; ks++) {
                unsigned a0, a1, a2, a3;
                unsigned p0, p1, p2, p3, q0, q1, q2, q3;
                asm volatile(
                    "ldmatrix.sync.aligned.m8n8.x4.shared.b16 {%0,%1,%2,%3}, [%4];"
                    : "=r"(a0), "=r"(a1), "=r"(a2), "=r"(a3)
                    : "r"(aOff + ks * 32));
                asm volatile(
                    "ldmatrix.sync.aligned.m8n8.x4.shared.b16 {%0,%1,%2,%3}, [%4];"
                    : "=r"(p0), "=r"(p1), "=r"(p2), "=r"(p3)
                    : "r"(bLo + ks * 32));
                asm volatile(
                    "ldmatrix.sync.aligned.m8n8.x4.shared.b16 {%0,%1,%2,%3}, [%4];"
                    : "=r"(q0), "=r"(q1), "=r"(q2), "=r"(q3)
                    : "r"(bLo + 16 * BROW + ks * 32));
                asm volatile(
                    "mma.sync.aligned.m16n8k32.row.col.s32.s8.s8.s32 "
                    "{%0,%1,%2,%3}, {%4,%5,%6,%7}, {%8,%9}, {%0,%1,%2,%3};\n"
                    : "+r"(acc[0][0]), "+r"(acc[0][1]), "+r"(acc[0][2]), "+r"(acc[0][3])
                    : "r"(a0), "r"(a1), "r"(a2), "r"(a3), "r"(p0), "r"(p1));
                asm volatile(
                    "mma.sync.aligned.m16n8k32.row.col.s32.s8.s8.s32 "
                    "{%0,%1,%2,%3}, {%4,%5,%6,%7}, {%8,%9}, {%0,%1,%2,%3};\n"
                    : "+r"(acc[1][0]), "+r"(acc[1][1]), "+r"(acc[1][2]), "+r"(acc[1][3])
                    : "r"(a0), "r"(a1), "r"(a2), "r"(a3), "r"(p2), "r"(p3));
                asm volatile(
                    "mma.sync.aligned.m16n8k32.row.col.s32.s8.s8.s32 "
                    "{%0,%1,%2,%3}, {%4,%5,%6,%7}, {%8,%9}, {%0,%1,%2,%3};\n"
                    : "+r"(acc[2][0]), "+r"(acc[2][1]), "+r"(acc[2][2]), "+r"(acc[2][3])
                    : "r"(a0), "r"(a1), "r"(a2), "r"(a3), "r"(q0), "r"(q1));
                asm volatile(
                    "mma.sync.aligned.m16n8k32.row.col.s32.s8.s8.s32 "
                    "{%0,%1,%2,%3}, {%4,%5,%6,%7}, {%8,%9}, {%0,%1,%2,%3};\n"
                    : "+r"(acc[3][0]), "+r"(acc[3][1]), "+r"(acc[3][2]), "+r"(acc[3][3])
                    : "r"(a0), "r"(a1), "r"(a2), "r"(a3), "r"(q2), "r"(q3));
            }

            if (g < G_DIM - 2) BAR_ARRIVE(3 + b);   // EMPTY[b]
        }

        // ---- epilogue ----
        const int m0 = wm * 16 + g4;
        const float isc0 = isc[m0];
        const float isc1 = isc[m0 + 8];
#pragma unroll
        for (int ns = 0; ns < 4; ns++) {
            const int n = n0 + ns * 8 + tg * 2;
            const float s1a = s1[n],   s1b = s1[n + 1];
            const float ba  = bias[n], bb  = bias[n + 1];
            out[ m0      * N_DIM + n    ] = (float)acc[ns][0] * isc0 * s1a + ba;
            out[ m0      * N_DIM + n + 1] = (float)acc[ns][1] * isc0 * s1b + bb;
            out[(m0 + 8) * N_DIM + n    ] = (float)acc[ns][2] * isc1 * s1a + ba;
            out[(m0 + 8) * N_DIM + n + 1] = (float)acc[ns][3] * isc1 * s1b + bb;
        }
    } else {
        // =================== PRODUCER: warps 4-7 ===================
        const int t    = tid - 128;          // 0..127
        const int brow = t >> 2;             // weight row 0..31
        const int bseg = t & 3;              // 128B segment of the group row
        const char* gRow = reinterpret_cast<const char*>(
            qw + (size_t)(n0 + brow) * K_DIM) + bseg * 128;
        // raw chunk c of thread t at c*2048 + t*16 (conflict-free both ways)
        const unsigned myRaw = sbase + (unsigned)t * 16u;
        const unsigned bSto  = (unsigned)brow * BROW + (unsigned)bseg * 32u;
        const int4* xb = reinterpret_cast<const int4*>(g_x_packed);

        // ---- prologue: stream raw groups 0 and 1 ----
#pragma unroll
        for (int s = 0; s < 2; s++) {
            const char* src = gRow + (size_t)s * 512;
#pragma unroll
            for (int c = 0; c < 8; c++)
                CP_ASYNC16(myRaw + OFF_RAW(s) + c * 2048u, src + c * 16);
            CP_COMMIT();
        }
        int s2v = s2s[n0 + brow];
        int zv  = s2z[n0 + brow];

        for (int g = 0; g < G_DIM; ++g) {
            const int b = g & 1;

            // x slice for A tile (L2-hot LDG, overlapped with EMPTY wait)
            int4 xr[4];
#pragma unroll
            for (int j = 0; j < 4; j++) {
                const int u = t + j * 128;
                xr[j] = xb[(u >> 3) * (K_DIM / 16) + g * 8 + (u & 7)];
            }

            if (g >= 2) BAR_SYNC(3 + b);     // wait EMPTY[b]
            if (g == G_DIM - 1) { CP_WAIT(0); } else { CP_WAIT(1); }

            // dequant 32 weights -> s8, 2 STS.128 into B[b]
            unsigned pk[8];
#pragma unroll
            for (int c = 0; c < 8; c++) {
                int4 q = *reinterpret_cast<const int4*>(
                    smem + OFF_RAW(b) + c * 2048 + t * 16);
                int w0 = q.x * s2v + zv;
                int w1 = q.y * s2v + zv;
                int w2 = q.z * s2v + zv;
                int w3 = q.w * s2v + zv;
                pk[c] = __byte_perm(__byte_perm((unsigned)w0, (unsigned)w1, 0x0040),
                                    __byte_perm((unsigned)w2, (unsigned)w3, 0x0040), 0x5410);
            }
            {
                unsigned char* dst = smem + OFF_B(b) + bSto;
                *reinterpret_cast<uint4*>(dst)      = make_uint4(pk[0], pk[1], pk[2], pk[3]);
                *reinterpret_cast<uint4*>(dst + 16) = make_uint4(pk[4], pk[5], pk[6], pk[7]);
            }
            // A tile stores
#pragma unroll
            for (int j = 0; j < 4; j++) {
                const int u = t + j * 128;
                *reinterpret_cast<int4*>(
                    smem + OFF_A(b) + (u >> 3) * BROW + (u & 7) * 16) = xr[j];
            }

            // refill raw[b] with group g+2
            if (g + 2 < G_DIM) {
                const char* src = gRow + (size_t)(g + 2) * 512;
#pragma unroll
                for (int c = 0; c < 8; c++)
                    CP_ASYNC16(myRaw + OFF_RAW(b) + c * 2048u, src + c * 16);
                CP_COMMIT();
            }
            // next group's scales
            if (g + 1 < G_DIM) {
                s2v = s2s[(g + 1) * N_DIM + n0 + brow];
                zv  = s2z[(g + 1) * N_DIM + n0 + brow];
            }

            asm volatile("membar.cta;" ::: "memory");
            BAR_ARRIVE(1 + b);               // FULL[b]
        }
    }
}

// ---------------------------------------------------------------------------
extern "C" void kernel_launch(void* const* d_in, const int* in_sizes, int n_in,
                              void* d_out, int out_size) {
    const int*   x    = (const int*)  d_in[0];  // [M,K] int32 (int8 values)
    const float* isc  = (const float*)d_in[1];  // [M]
    // d_in[2] = input_sum (unused)
    const int*   qw   = (const int*)  d_in[3];  // [N,K] int32 (uint4 values)
    const int*   s2s  = (const int*)  d_in[4];  // [G,N]
    const int*   s2z  = (const int*)  d_in[5];  // [G,N]
    const float* s1   = (const float*)d_in[6];  // [N]
    const float* bias = (const float*)d_in[7];  // [N]
    float* out = (float*)d_out;

    cudaFuncSetAttribute(w4a8_gemm_kernel,
                         cudaFuncAttributeMaxDynamicSharedMemorySize, SMEM_TOTAL);

    pack_x_kernel<<<(M_DIM * K_DIM / 4 + 255) / 256, 256>>>(x);
    w4a8_gemm_kernel<<<N_DIM / NT, THREADS, SMEM_TOTAL>>>(qw, s2s, s2z, isc, s1, bias, out);
}

// round 14
// speedup vs baseline: 1.2459x; 1.2459x over previous
#include <cuda_runtime.h>
#include <stdint.h>

// ---------------------------------------------------------------------------
// W4A8 per-group GEMM, legacy IMMA (tcgen05 rejected by sm_103 PTX target).
//   w_int8[o,k] = q4[o,k]*s2[g,o] + z[g,o]   (exact int8, |w| <= 105)
//   acc[m,o]    = sum_k x_i8[m,k]*w_int8[o,k]  (s32 mma.m16n8k32)
//   out[m,o]    = acc * isc[m] * s1[o] + bias[o]
//
// Round 14: R8 datapath (NT=32, 448 CTAs, 256 thr, ldmatrix, register-
// prefetched weights) with TRIPLE-buffered A+B tiles and a straight-line
// loop body: prefetch(g+2) LDG, dequant(g+1)+STS -> buf[(g+1)%3], MMA(g)
// from buf[g%3], ONE sync. Store phase schedules into the MMA shadow
// (R6's interleave, fixed: A stays in smem — R6's failure was per-MMA A LDG).
// ---------------------------------------------------------------------------

#define M_DIM 64
#define K_DIM 4096
#define N_DIM 14336
#define G_DIM 32
#define GS    128          // K per group
#define NT    32           // output channels per CTA -> 448 CTAs
#define BROW  144          // padded s8 tile row (conflict-free, validated)
#define THREADS 256
#define TILE_A (M_DIM * BROW)   // 9216
#define TILE_B (NT * BROW)      // 4608

__device__ __forceinline__ unsigned smem_u32(const void* p) {
    unsigned a;
    asm("{ .reg .u64 t; cvta.to.shared.u64 t, %1; cvt.u32.u64 %0, t; }" : "=r"(a) : "l"(p));
    return a;
}

// int8-packed activations [M][K] (256 KB static scratch; validated R1-R8)
__device__ __align__(16) unsigned int g_x_packed[M_DIM * K_DIM / 4];

__global__ void pack_x_kernel(const int* __restrict__ x) {
    int idx = blockIdx.x * blockDim.x + threadIdx.x;
    if (idx >= M_DIM * K_DIM / 4) return;
    const int4 v = reinterpret_cast<const int4*>(x)[idx];
    unsigned a = __byte_perm((unsigned)v.x, (unsigned)v.y, 0x0040);
    unsigned b = __byte_perm((unsigned)v.z, (unsigned)v.w, 0x0040);
    g_x_packed[idx] = __byte_perm(a, b, 0x5410);
}

// ---- main GEMM ---------------------------------------------------------------
__global__ __launch_bounds__(THREADS, 3)
void w4a8_gemm_kernel(const int*   __restrict__ qw,    // [N,K] int32 (0..15)
                      const int*   __restrict__ s2s,   // [G,N]
                      const int*   __restrict__ s2z,   // [G,N]
                      const float* __restrict__ isc,   // [M]
                      const float* __restrict__ s1,    // [N]
                      const float* __restrict__ bias,  // [N]
                      float*       __restrict__ out)   // [M,N]
{
    __shared__ __align__(16) unsigned char sA[3][TILE_A]; // x tiles 64x128 s8
    __shared__ __align__(16) unsigned char sB[3][TILE_B]; // w tiles 32x128 s8

    const int tid = threadIdx.x;
    const int n0  = blockIdx.x * NT;

    // B dequant mapping: thread -> (weight row 0..31, 16-int segment 0..7)
    const int brow = tid >> 3;
    const int bseg = tid & 7;
    const int4* qbase = reinterpret_cast<const int4*>(qw)
                      + (size_t)(n0 + brow) * (K_DIM / 4) + bseg * 4;
    const unsigned bSto = (unsigned)brow * BROW + (unsigned)bseg * 16u;

    // A producer mapping: thread -> two int4 slots (64 rows x 8 chunks)
    const int4* xb = reinterpret_cast<const int4*>(g_x_packed);

    // MMA mapping: 8 warps as 4(M) x 2(N); warp tile 16m x 16n (R8 validated)
    const int warp = tid >> 5, lane = tid & 31;
    const int wm = warp >> 1;
    const int wn = warp & 1;
    const int g4 = lane >> 2, tg = lane & 3;

    const unsigned sAu = smem_u32(&sA[0][0]);
    const unsigned sBu = smem_u32(&sB[0][0]);
    const unsigned aFrag = sAu + (unsigned)(wm * 16 + (lane & 15)) * BROW
                               + (unsigned)((lane >> 4) & 1) * 16;
    const unsigned bFrag = sBu + (unsigned)(wn * 16 + ((lane >> 4) & 1) * 8 + (lane & 7)) * BROW
                               + (unsigned)((lane >> 3) & 1) * 16;

    int acc[2][4];
#pragma unroll
    for (int i = 0; i < 2; i++)
#pragma unroll
        for (int j = 0; j < 4; j++) acc[i][j] = 0;

    int4 qr[4], qn[4];   // raw weights for tile g+1 / g+2
    int4 xr[2], xn[2];   // packed-x slots for tile g+1 / g+2
    int  s2v, zv, s2n, zn;

    // ---- prologue: dequant group 0 directly into buf 0 ----
    {
        int4 q0[4];
#pragma unroll
        for (int j = 0; j < 4; j++) q0[j] = qbase[j];
        int4 x0[2];
#pragma unroll
        for (int j = 0; j < 2; j++) {
            const int u = tid + j * 256;
            x0[j] = xb[(u >> 3) * (K_DIM / 16) + (u & 7)];
        }
        const int s20 = s2s[n0 + brow];
        const int z0  = s2z[n0 + brow];
        unsigned pk[4];
#pragma unroll
        for (int j = 0; j < 4; j++) {
            int w0 = q0[j].x * s20 + z0;
            int w1 = q0[j].y * s20 + z0;
            int w2 = q0[j].z * s20 + z0;
            int w3 = q0[j].w * s20 + z0;
            pk[j] = __byte_perm(__byte_perm((unsigned)w0, (unsigned)w1, 0x0040),
                                __byte_perm((unsigned)w2, (unsigned)w3, 0x0040), 0x5410);
        }
        *reinterpret_cast<uint4*>(&sB[0][bSto]) = make_uint4(pk[0], pk[1], pk[2], pk[3]);
#pragma unroll
        for (int j = 0; j < 2; j++) {
            const int u = tid + j * 256;
            *reinterpret_cast<int4*>(&sA[0][(u >> 3) * BROW + (u & 7) * 16]) = x0[j];
        }
        // prefetch group 1 into (qr, xr)
        const int4* qp = qbase + (GS / 4);
#pragma unroll
        for (int j = 0; j < 4; j++) qr[j] = qp[j];
#pragma unroll
        for (int j = 0; j < 2; j++) {
            const int u = tid + j * 256;
            xr[j] = xb[(u >> 3) * (K_DIM / 16) + (GS / 16) + (u & 7)];
        }
        s2v = s2s[N_DIM + n0 + brow];
        zv  = s2z[N_DIM + n0 + brow];
    }
    __syncthreads();

    int rbuf = 0, wbuf = 1;

    for (int g = 0; g < G_DIM; ++g) {
        // ---- 1) prefetch raw tile g+2 (clamped; long-latency first) ----
        const int gl = (g + 2 < G_DIM) ? (g + 2) : (G_DIM - 1);
        {
            const int4* qp = qbase + gl * (GS / 4);
#pragma unroll
            for (int j = 0; j < 4; j++) qn[j] = qp[j];
#pragma unroll
            for (int j = 0; j < 2; j++) {
                const int u = tid + j * 256;
                xn[j] = xb[(u >> 3) * (K_DIM / 16) + gl * (GS / 16) + (u & 7)];
            }
            s2n = s2s[gl * N_DIM + n0 + brow];
            zn  = s2z[gl * N_DIM + n0 + brow];
        }

        // ---- 2) dequant tile g+1 -> STS into buf[wbuf] (skipped on last) ----
        if (g + 1 < G_DIM) {
            unsigned pk[4];
#pragma unroll
            for (int j = 0; j < 4; j++) {
                int w0 = qr[j].x * s2v + zv;
                int w1 = qr[j].y * s2v + zv;
                int w2 = qr[j].z * s2v + zv;
                int w3 = qr[j].w * s2v + zv;
                pk[j] = __byte_perm(__byte_perm((unsigned)w0, (unsigned)w1, 0x0040),
                                    __byte_perm((unsigned)w2, (unsigned)w3, 0x0040), 0x5410);
            }
            *reinterpret_cast<uint4*>(&sB[wbuf][bSto]) = make_uint4(pk[0], pk[1], pk[2], pk[3]);
#pragma unroll
            for (int j = 0; j < 2; j++) {
                const int u = tid + j * 256;
                *reinterpret_cast<int4*>(&sA[wbuf][(u >> 3) * BROW + (u & 7) * 16]) = xr[j];
            }
        }

        // ---- 3) MMA tile g from buf[rbuf] (interleaves with 1&2 above) ----
        const unsigned aOff = aFrag + (unsigned)rbuf * TILE_A;
        const unsigned bOff = bFrag + (unsigned)rbuf * TILE_B;
#pragma unroll
        for (int ks = 0; ks < 4; ks++) {
            unsigned a0, a1, a2, a3, b0, b1, b2, b3;
            asm volatile(
                "ldmatrix.sync.aligned.m8n8.x4.shared.b16 {%0,%1,%2,%3}, [%4];"
                : "=r"(a0), "=r"(a1), "=r"(a2), "=r"(a3)
                : "r"(aOff + ks * 32));
            asm volatile(
                "ldmatrix.sync.aligned.m8n8.x4.shared.b16 {%0,%1,%2,%3}, [%4];"
                : "=r"(b0), "=r"(b1), "=r"(b2), "=r"(b3)
                : "r"(bOff + ks * 32));
            asm volatile(
                "mma.sync.aligned.m16n8k32.row.col.s32.s8.s8.s32 "
                "{%0,%1,%2,%3}, {%4,%5,%6,%7}, {%8,%9}, {%0,%1,%2,%3};\n"
                : "+r"(acc[0][0]), "+r"(acc[0][1]), "+r"(acc[0][2]), "+r"(acc[0][3])
                : "r"(a0), "r"(a1), "r"(a2), "r"(a3), "r"(b0), "r"(b1));
            asm volatile(
                "mma.sync.aligned.m16n8k32.row.col.s32.s8.s8.s32 "
                "{%0,%1,%2,%3}, {%4,%5,%6,%7}, {%8,%9}, {%0,%1,%2,%3};\n"
                : "+r"(acc[1][0]), "+r"(acc[1][1]), "+r"(acc[1][2]), "+r"(acc[1][3])
                : "r"(a0), "r"(a1), "r"(a2), "r"(a3), "r"(b2), "r"(b3));
        }

        // ---- rotate prefetch registers and buffers ----
#pragma unroll
        for (int j = 0; j < 4; j++) qr[j] = qn[j];
#pragma unroll
        for (int j = 0; j < 2; j++) xr[j] = xn[j];
        s2v = s2n; zv = zn;
        rbuf = (rbuf == 2) ? 0 : rbuf + 1;
        wbuf = (wbuf == 2) ? 0 : wbuf + 1;

        __syncthreads();   // one barrier per group
    }

    // ---- epilogue: out = acc * isc[m] * s1[n] + bias[n] ----
    const int m0 = wm * 16 + g4;
    const float isc0 = isc[m0];
    const float isc1 = isc[m0 + 8];
#pragma unroll
    for (int ns = 0; ns < 2; ns++) {
        const int n = n0 + wn * 16 + ns * 8 + tg * 2;
        const float s1a = s1[n],   s1b = s1[n + 1];
        const float ba  = bias[n], bb  = bias[n + 1];
        out[ m0      * N_DIM + n    ] = (float)acc[ns][0] * isc0 * s1a + ba;
        out[ m0      * N_DIM + n + 1] = (float)acc[ns][1] * isc0 * s1b + bb;
        out[(m0 + 8) * N_DIM + n    ] = (float)acc[ns][2] * isc1 * s1a + ba;
        out[(m0 + 8) * N_DIM + n + 1] = (float)acc[ns][3] * isc1 * s1b + bb;
    }
}

// ---------------------------------------------------------------------------
extern "C" void kernel_launch(void* const* d_in, const int* in_sizes, int n_in,
                              void* d_out, int out_size) {
    const int*   x    = (const int*)  d_in[0];  // [M,K] int32 (int8 values)
    const float* isc  = (const float*)d_in[1];  // [M]
    // d_in[2] = input_sum (unused)
    const int*   qw   = (const int*)  d_in[3];  // [N,K] int32 (uint4 values)
    const int*   s2s  = (const int*)  d_in[4];  // [G,N]
    const int*   s2z  = (const int*)  d_in[5];  // [G,N]
    const float* s1   = (const float*)d_in[6];  // [N]
    const float* bias = (const float*)d_in[7];  // [N]
    float* out = (float*)d_out;

    pack_x_kernel<<<(M_DIM * K_DIM / 4 + 255) / 256, 256>>>(x);
    w4a8_gemm_kernel<<<N_DIM / NT, THREADS>>>(qw, s2s, s2z, isc, s1, bias, out);
}